// round 12
// baseline (speedup 1.0000x reference)
#include <cuda_runtime.h>
#include <math.h>

// FocalCTCLoss: B=256, T=1024, V=128, L=64, S=129, blank=127.
// LINEAR-domain fp32 CTC DP with exact power-of-2 rescaling (no MUFU in DP).
// Coalesced float4 row loads -> double-buffered smem staging (8-row blocks)
// -> label gathers via LDS. Z from staged data via transposed smem sums.
// R12: TWO-block-deep register prefetch (rvA/rvB) so each block's global
// loads get ~2 block-periods of latency cover (DRAM-latency was the wall).
// CTA = 128 thr: w0=fwd e0, w1=bwd e0, w2=fwd e1, w3=bwd e1. Grid 128.

#define B_ 256
#define T_ 1024
#define V_ 128
#define L_ 64
#define EPS_ 1e-7f
#define NEG (-1e30f)
#define LN2_ 0.6931471805599453f

__device__ float g_focal[B_];
__device__ unsigned int g_count;   // zero-init at load; reset by last CTA

__device__ __forceinline__ float ex2(float x) { float r; asm("ex2.approx.ftz.f32 %0,%1;" : "=f"(r) : "f"(x)); return r; }
__device__ __forceinline__ float lg2(float x) { float r; asm("lg2.approx.ftz.f32 %0,%1;" : "=f"(r) : "f"(x)); return r; }

__global__ void __launch_bounds__(128, 1) ctc_kernel(const int* __restrict__ y_true,
                                                     const float* __restrict__ y_pred,
                                                     float* __restrict__ out) {
    __shared__ float4 sstage4[4][2][8][32];   // [warp][buf][row][lane] 32KB
    __shared__ float szp[4][16][33];          // Z row-partials (transposed sum)
    __shared__ float sbeta[2][132];           // bwd log2(beta') per state
    __shared__ float szHalf[4];               // per-warp Sum lg2(Z) halves
    __shared__ float sfocal[2];
    __shared__ float sred[4];
    __shared__ unsigned int sIsLast;

    const int lane = threadIdx.x & 31;
    const int wid = threadIdx.x >> 5;
    const bool fwd = ((wid & 1) == 0);
    const int e = wid >> 1;
    const int b = (blockIdx.x << 1) + e;

    const float4* yrow4 = reinterpret_cast<const float4*>(y_pred + (size_t)b * (T_ * V_));

    // Lane l owns states 4l..4l+3 (lane 31 also s=128).
    //  s=4l: blank  s=4l+1: label 2l  s=4l+2: blank  s=4l+3: label 2l+1
    const int* lr = y_true + b * L_;
    const int lab1 = lr[2 * lane];
    const int lab3 = lr[2 * lane + 1];
    const int labp = (lane > 0) ? lr[2 * lane - 1] : 0;
    const float sk1 = (lane > 0 && lab1 != labp) ? 1.0f : 0.0f;
    const float sk3 = (lab3 != lab1) ? 1.0f : 0.0f;

    const int dir = fwd ? 1 : -1;
    const int t0 = fwd ? 0 : 1023;
    const int edge = fwd ? 0 : 31;

    float* const sstW = reinterpret_cast<float*>(&sstage4[wid][0][0][0]);

    // Two-block-deep register rings: rvA = even blocks, rvB = odd blocks.
    float4 rvA[8], rvB[8];
#pragma unroll
    for (int r = 0; r < 8; ++r) rvA[r] = yrow4[(t0 + dir * r) * 32 + lane];
#pragma unroll
    for (int r = 0; r < 8; ++r) rvB[r] = yrow4[(t0 + dir * (8 + r)) * 32 + lane];

    float a0 = 0.f, a1 = 0.f, a2 = 0.f, a3 = 0.f, a4 = 0.f;
    int K = 0;
    float sc = (lane == edge) ? 0.0f : 1.0f;
    float qB, q1, q3, pqB, pq1, pq3;
    float zpart = 0.f;

    // stage block c from RING, then refill RING with block c+2 (rows are
    // always in [0,1023] for c+2 <= 65, i.e. all 64 processed blocks).
#define STAGE8(c, RING)                                                       \
    {                                                                         \
        float4* dst = reinterpret_cast<float4*>(sst);                         \
        _Pragma("unroll")                                                     \
        for (int r = 0; r < 8; ++r) {                                         \
            float4 y = RING[r];                                               \
            dst[r * 32 + lane] = y;                                           \
            szp[wid][((c) * 8 + r) & 15][lane] = (y.x + y.y) + (y.z + y.w);   \
        }                                                                     \
        __syncwarp();                                                         \
    }

#define PREFETCH8(c, RING)                                                    \
    {                                                                         \
        _Pragma("unroll")                                                     \
        for (int r = 0; r < 8; ++r)                                           \
            RING[r] = yrow4[(t0 + dir * (((c) + 2) * 8 + r)) * 32 + lane];    \
    }

#define TRANSPOSE_Z()                                                         \
    {                                                                         \
        int rr = lane & 15;                                                   \
        int j0 = (lane >> 4) << 4;                                            \
        float Zs0 = 0.f, Zs1 = 0.f;                                           \
        _Pragma("unroll")                                                     \
        for (int j = 0; j < 16; j += 2) {                                     \
            Zs0 += szp[wid][rr][j0 + j];                                      \
            Zs1 += szp[wid][rr][j0 + j + 1];                                  \
        }                                                                     \
        float Zs = Zs0 + Zs1;                                                 \
        Zs += __shfl_down_sync(0xffffffffu, Zs, 16);                          \
        if (lane < 16) zpart += lg2(Zs + V_ * EPS_);                          \
        __syncwarp();                                                         \
    }

#define QLDS_TO(r, oB, o1, o3)                                                \
    {                                                                         \
        const float* rw = sst + (r) * 128;                                    \
        oB = rw[127] + EPS_; o1 = rw[lab1] + EPS_; o3 = rw[lab3] + EPS_;      \
    }

#define RENORM(SHFL_EXPR)                                                     \
    {                                                                         \
        float m = fmaxf(fmaxf(fmaxf(a0, a1), fmaxf(a2, a3)), a4);             \
        int ee = (int)(__float_as_uint(m) >> 23);                             \
        int ec = (ee > 0) ? ee : 127;                                         \
        K += ec - 127;                                                        \
        float rsc = __int_as_float((unsigned)(254 - ec) << 23);               \
        a0 *= rsc; a1 *= rsc; a2 *= rsc; a3 *= rsc; a4 *= rsc;                \
        int Kn = SHFL_EXPR;                                                   \
        int d = Kn - K; if (d > 127) d = 127;                                 \
        sc = (d < -126) ? 0.0f : __int_as_float((unsigned)(d + 127) << 23);   \
        if (lane == edge) sc = 0.0f;                                          \
    }

#define FWD_DP()                                                              \
    {                                                                         \
        float hi1 = __shfl_up_sync(0xffffffffu, a3, 1) * sc;                  \
        float n0 = (a0 + hi1) * qB;                                           \
        float n1 = fmaf(sk1, hi1, a0 + a1) * q1;                              \
        float n2 = (a1 + a2) * qB;                                            \
        float n3 = fmaf(sk3, a1, a2 + a3) * q3;                               \
        float n4 = (a3 + a4) * qB;                                            \
        a0 = n0; a1 = n1; a2 = n2; a3 = n3;                                   \
        a4 = (lane == 31) ? n4 : 0.0f;                                        \
    }

// FWD pipelined step: prefetch q(rnext) while DP consumes current q.
#define FWD_STEP_PIPE(rnext)                                                  \
    {                                                                         \
        float tB, t1, t3;                                                     \
        QLDS_TO(rnext, tB, t1, t3);                                           \
        FWD_DP();                                                             \
        qB = tB; q1 = t1; q3 = t3;                                            \
    }

#define BWD_DP()                                                              \
    {                                                                         \
        float c1 = a1 * pq1;                                                  \
        float c3 = a3 * pq3;                                                  \
        float cB2 = a2 * pqB;                                                 \
        float w = c1 * sk1;                                                   \
        float wd = __shfl_down_sync(0xffffffffu, w, 1) * sc;                  \
        float b0d = __shfl_down_sync(0xffffffffu, a0, 1) * sc;                \
        float t1 = (lane == 31) ? a4 : b0d;                                   \
        float t2 = (lane == 31) ? 0.0f : wd;                                  \
        float n0 = fmaf(a0, pqB, c1);                                         \
        float n1 = fmaf(c3, sk3, c1 + cB2);                                   \
        float n2 = cB2 + c3;                                                  \
        float n3 = fmaf(t1, pqB, c3 + t2);                                    \
        float n4 = a4 * pqB;                                                  \
        a0 = n0; a1 = n1; a2 = n2; a3 = n3; a4 = n4;                          \
        pqB = qB; pq1 = q1; pq3 = q3;                                         \
    }

#define SH_UP   __shfl_up_sync(0xffffffffu, K, 1)
#define SH_DN   __shfl_down_sync(0xffffffffu, K, 1)

#define FWD_BLOCK(c, RING)                                                    \
    {                                                                         \
        float* sst = sstW + ((c) & 1) * 1024;                                 \
        STAGE8(c, RING);                                                      \
        PREFETCH8(c, RING);                                                   \
        QLDS_TO(0, qB, q1, q3);                                               \
        FWD_STEP_PIPE(1); FWD_STEP_PIPE(2); FWD_STEP_PIPE(3);                 \
        FWD_STEP_PIPE(4); FWD_STEP_PIPE(5); FWD_STEP_PIPE(6);                 \
        FWD_STEP_PIPE(7);                                                     \
        FWD_DP(); RENORM(SH_UP);                                              \
    }

#define BWD_BLOCK(c, RING)                                                    \
    {                                                                         \
        float* sst = sstW + ((c) & 1) * 1024;                                 \
        STAGE8(c, RING);                                                      \
        PREFETCH8(c, RING);                                                   \
        QLDS_TO(0, qB, q1, q3); BWD_DP();                                     \
        QLDS_TO(1, qB, q1, q3); BWD_DP();                                     \
        QLDS_TO(2, qB, q1, q3); BWD_DP();                                     \
        QLDS_TO(3, qB, q1, q3); BWD_DP();                                     \
        QLDS_TO(4, qB, q1, q3); BWD_DP();                                     \
        QLDS_TO(5, qB, q1, q3); BWD_DP();                                     \
        QLDS_TO(6, qB, q1, q3); BWD_DP();                                     \
        QLDS_TO(7, qB, q1, q3); BWD_DP();                                     \
        RENORM(SH_DN);                                                        \
    }

    if (fwd) {
        {   // block 0: row 0 is init, rows 1..7 are DP steps 1..7
            float* sst = sstW;
            STAGE8(0, rvA);
            PREFETCH8(0, rvA);
            QLDS_TO(0, qB, q1, q3);
            if (lane == 0) { a0 = qB; a1 = q1; }            // alpha'_0
            QLDS_TO(1, qB, q1, q3);
            FWD_STEP_PIPE(2); FWD_STEP_PIPE(3); FWD_STEP_PIPE(4);
            FWD_STEP_PIPE(5); FWD_STEP_PIPE(6); FWD_STEP_PIPE(7);
            FWD_DP(); RENORM(SH_UP);
        }
        for (int cp = 0; cp < 31; ++cp) {                   // blocks 1..62
            const int c = 2 * cp + 1;
            FWD_BLOCK(c, rvB); TRANSPOSE_Z();
            FWD_BLOCK(c + 1, rvA);
        }
        FWD_BLOCK(63, rvB); TRANSPOSE_Z();
    } else {
        {   // block 0: row 0 loads q(1023) into pq + init, rows 1..7 DP
            float* sst = sstW;
            STAGE8(0, rvA);
            PREFETCH8(0, rvA);
            QLDS_TO(0, qB, q1, q3);
            pqB = qB; pq1 = q1; pq3 = q3;
            if (lane == 31) { a3 = 1.0f; a4 = 1.0f; }       // beta_1023
            QLDS_TO(1, qB, q1, q3); BWD_DP();
            QLDS_TO(2, qB, q1, q3); BWD_DP();
            QLDS_TO(3, qB, q1, q3); BWD_DP();
            QLDS_TO(4, qB, q1, q3); BWD_DP();
            QLDS_TO(5, qB, q1, q3); BWD_DP();
            QLDS_TO(6, qB, q1, q3); BWD_DP();
            QLDS_TO(7, qB, q1, q3); BWD_DP();
            RENORM(SH_DN);
        }
        for (int cp = 0; cp < 31; ++cp) {                   // blocks 1..62
            const int c = 2 * cp + 1;
            BWD_BLOCK(c, rvB); TRANSPOSE_Z();
            BWD_BLOCK(c + 1, rvA);
        }
        BWD_BLOCK(63, rvB); TRANSPOSE_Z();
    }

    // per-warp Sum lg2(Z) over its 512 timesteps (lanes >=16 hold 0)
#pragma unroll
    for (int off = 16; off; off >>= 1)
        zpart += __shfl_xor_sync(0xffffffffu, zpart, off);
    if (lane == 0) szHalf[wid] = zpart;

    if (!fwd) {
        float Kf = (float)K;
        sbeta[e][4 * lane + 0] = lg2(a0) + Kf;
        sbeta[e][4 * lane + 1] = lg2(a1) + Kf;
        sbeta[e][4 * lane + 2] = lg2(a2) + Kf;
        sbeta[e][4 * lane + 3] = lg2(a3) + Kf;
        if (lane == 31) sbeta[e][128] = lg2(a4) + Kf;
    }
    __syncthreads();

    if (fwd) {
        // loglik = (LSE_s(log2 alpha'_511 + log2 beta'_511) - szTot) * ln2
        float Kf = (float)K;
        float c0 = lg2(a0) + Kf + sbeta[e][4 * lane + 0];
        float c1 = lg2(a1) + Kf + sbeta[e][4 * lane + 1];
        float c2 = lg2(a2) + Kf + sbeta[e][4 * lane + 2];
        float c3 = lg2(a3) + Kf + sbeta[e][4 * lane + 3];
        float c4 = (lane == 31) ? (lg2(a4) + Kf + sbeta[e][128]) : NEG;
        float m = fmaxf(fmaxf(fmaxf(c0, c1), fmaxf(c2, c3)), c4);
#pragma unroll
        for (int off = 16; off; off >>= 1)
            m = fmaxf(m, __shfl_xor_sync(0xffffffffu, m, off));
        float s = ex2(c0 - m) + ex2(c1 - m) + ex2(c2 - m) + ex2(c3 - m) + ex2(c4 - m);
#pragma unroll
        for (int off = 16; off; off >>= 1)
            s += __shfl_xor_sync(0xffffffffu, s, off);
        if (lane == 0) {
            float szTot = szHalf[wid] + szHalf[wid + 1];
            float loglik = (m + lg2(s) - szTot) * LN2_;
            float loss = -loglik;
            float p = expf(-loss);
            float om = 1.0f - p;
            sfocal[e] = 0.25f * om * om * loss;
        }
    }
    __syncthreads();

    // ---- fused mean: last CTA reduces all 256 focal values in parallel ----
    if (threadIdx.x == 0) {
        const int b0 = blockIdx.x << 1;
        g_focal[b0] = sfocal[0];
        g_focal[b0 + 1] = sfocal[1];
        __threadfence();
        unsigned int old = atomicAdd(&g_count, 1u);
        sIsLast = (old == gridDim.x - 1) ? 1u : 0u;
    }
    __syncthreads();
    if (sIsLast) {
        float v = g_focal[threadIdx.x] + g_focal[threadIdx.x + 128];
#pragma unroll
        for (int off = 16; off; off >>= 1)
            v += __shfl_xor_sync(0xffffffffu, v, off);
        if (lane == 0) sred[wid] = v;
        __syncthreads();
        if (threadIdx.x == 0) {
            out[0] = ((sred[0] + sred[1]) + (sred[2] + sred[3])) * (1.0f / (float)B_);
            g_count = 0;             // reset for next graph replay
        }
    }
}

extern "C" void kernel_launch(void* const* d_in, const int* in_sizes, int n_in,
                              void* d_out, int out_size) {
    const int* y_true;
    const float* y_pred;
    if (in_sizes[0] == B_ * L_) {
        y_true = (const int*)d_in[0];
        y_pred = (const float*)d_in[1];
    } else {
        y_true = (const int*)d_in[1];
        y_pred = (const float*)d_in[0];
    }
    ctc_kernel<<<B_ / 2, 128>>>(y_true, y_pred, (float*)d_out);
}

// round 13
// speedup vs baseline: 1.0157x; 1.0157x over previous
#include <cuda_runtime.h>
#include <math.h>

// FocalCTCLoss: B=256, T=1024, V=128, L=64, S=129, blank=127.
// LINEAR-domain fp32 CTC DP with exact power-of-2 rescaling.
// R13: WARP SPECIALIZATION. Per (element, direction): a producer warp
// (LDG float4 rows -> STS smem staging, Z row-partials + transposed sums)
// and a DP warp (LDS label gathers + recurrence only). Lockstep
// double-buffer, one named bar.sync(id,64) per 8-row block.
// CTA = 256 thr: w0-3 = DP pairs (fwd e0, bwd e0, fwd e1, bwd e1),
// w4-7 = matching producers. Grid 128 (1 CTA/SM, 2 warps/SMSP).

#define B_ 256
#define T_ 1024
#define V_ 128
#define L_ 64
#define EPS_ 1e-7f
#define NEG (-1e30f)
#define LN2_ 0.6931471805599453f

__device__ float g_focal[B_];
__device__ unsigned int g_count;   // zero-init at load; reset by last CTA

__device__ __forceinline__ float ex2(float x) { float r; asm("ex2.approx.ftz.f32 %0,%1;" : "=f"(r) : "f"(x)); return r; }
__device__ __forceinline__ float lg2(float x) { float r; asm("lg2.approx.ftz.f32 %0,%1;" : "=f"(r) : "f"(x)); return r; }

#define NBAR(id) asm volatile("bar.sync %0, %1;" :: "r"(id), "r"(64) : "memory")

__global__ void __launch_bounds__(256, 1) ctc_kernel(const int* __restrict__ y_true,
                                                     const float* __restrict__ y_pred,
                                                     float* __restrict__ out) {
    __shared__ float4 sstage4[4][2][8][32];   // [pair][buf][row][lane] 32KB
    __shared__ float szp[4][16][33];          // Z row-partials (producer-private)
    __shared__ float sbeta[2][132];           // bwd log2(beta') per state
    __shared__ float szHalf[4];               // per-pair Sum lg2(Z) halves
    __shared__ float sfocal[2];
    __shared__ float sred[8];
    __shared__ unsigned int sIsLast;

    const int lane = threadIdx.x & 31;
    const int wid = threadIdx.x >> 5;
    const bool isProd = (wid >= 4);
    const int p = isProd ? (wid - 4) : wid;   // pair index 0..3
    const bool fwd = ((p & 1) == 0);
    const int e = p >> 1;
    const int b = (blockIdx.x << 1) + e;
    const int barid = p + 1;

    const int dir = fwd ? 1 : -1;
    const int t0 = fwd ? 0 : 1023;

    float* const sstP = reinterpret_cast<float*>(&sstage4[p][0][0][0]);

    if (isProd) {
        // ================= PRODUCER warp =================
        const float4* yrow4 =
            reinterpret_cast<const float4*>(y_pred + (size_t)b * (T_ * V_));
        float4 reg[8];
        float zpart = 0.f;

#define PLOAD(c)                                                              \
        {                                                                     \
            _Pragma("unroll")                                                 \
            for (int r = 0; r < 8; ++r)                                       \
                reg[r] = yrow4[(t0 + dir * ((c) * 8 + r)) * 32 + lane];       \
        }

#define PSTORE(c)                                                             \
        {                                                                     \
            float4* dst = reinterpret_cast<float4*>(sstP + ((c) & 1) * 1024); \
            _Pragma("unroll")                                                 \
            for (int r = 0; r < 8; ++r) {                                     \
                float4 y = reg[r];                                            \
                dst[r * 32 + lane] = y;                                       \
                szp[p][((c) * 8 + r) & 15][lane] = (y.x + y.y) + (y.z + y.w); \
            }                                                                 \
            __syncwarp();                                                     \
        }

#define TRANSPOSE_Z()                                                         \
        {                                                                     \
            int rr = lane & 15;                                               \
            int j0 = (lane >> 4) << 4;                                        \
            float Zs0 = 0.f, Zs1 = 0.f;                                       \
            _Pragma("unroll")                                                 \
            for (int j = 0; j < 16; j += 2) {                                 \
                Zs0 += szp[p][rr][j0 + j];                                    \
                Zs1 += szp[p][rr][j0 + j + 1];                                \
            }                                                                 \
            float Zs = Zs0 + Zs1;                                             \
            Zs += __shfl_down_sync(0xffffffffu, Zs, 16);                      \
            if (lane < 16) zpart += lg2(Zs + V_ * EPS_);                      \
            __syncwarp();                                                     \
        }

        PLOAD(0); PSTORE(0); PLOAD(1);
        NBAR(barid);                               // buf0 = block 0 ready
        for (int i = 0; i < 63; ++i) {
            PSTORE(i + 1);                         // stage block i+1 (other buf)
            if ((i & 1) == 0) TRANSPOSE_Z();       // blocks i,i+1 row-sums done
            PLOAD(i + 2);                          // rows always in [0,1023]
            NBAR(barid);
        }
        NBAR(barid);                               // i = 63: nothing to stage

        // zpart held in lanes 0..15
#pragma unroll
        for (int off = 16; off; off >>= 1)
            zpart += __shfl_xor_sync(0xffffffffu, zpart, off);
        if (lane == 0) szHalf[p] = zpart;
    } else {
        // ================= DP warp =================
        const int* lr = y_true + b * L_;
        const int lab1 = lr[2 * lane];
        const int lab3 = lr[2 * lane + 1];
        const int labp = (lane > 0) ? lr[2 * lane - 1] : 0;
        const float sk1 = (lane > 0 && lab1 != labp) ? 1.0f : 0.0f;
        const float sk3 = (lab3 != lab1) ? 1.0f : 0.0f;
        const int edge = fwd ? 0 : 31;

        float a0 = 0.f, a1 = 0.f, a2 = 0.f, a3 = 0.f, a4 = 0.f;
        int K = 0;
        float sc = (lane == edge) ? 0.0f : 1.0f;
        float qB, q1, q3, pqB, pq1, pq3;

#define QLDS_TO(r, oB, o1, o3)                                                \
        {                                                                     \
            const float* rw = sst + (r) * 128;                                \
            oB = rw[127] + EPS_; o1 = rw[lab1] + EPS_; o3 = rw[lab3] + EPS_;  \
        }

#define RENORM(SHFL_EXPR)                                                     \
        {                                                                     \
            float m = fmaxf(fmaxf(fmaxf(a0, a1), fmaxf(a2, a3)), a4);         \
            int ee = (int)(__float_as_uint(m) >> 23);                         \
            int ec = (ee > 0) ? ee : 127;                                     \
            K += ec - 127;                                                    \
            float rsc = __int_as_float((unsigned)(254 - ec) << 23);           \
            a0 *= rsc; a1 *= rsc; a2 *= rsc; a3 *= rsc; a4 *= rsc;            \
            int Kn = SHFL_EXPR;                                               \
            int d = Kn - K; if (d > 127) d = 127;                             \
            sc = (d < -126) ? 0.0f : __int_as_float((unsigned)(d + 127) << 23); \
            if (lane == edge) sc = 0.0f;                                      \
        }

#define FWD_DP()                                                              \
        {                                                                     \
            float hi1 = __shfl_up_sync(0xffffffffu, a3, 1) * sc;              \
            float n0 = (a0 + hi1) * qB;                                       \
            float n1 = fmaf(sk1, hi1, a0 + a1) * q1;                          \
            float n2 = (a1 + a2) * qB;                                        \
            float n3 = fmaf(sk3, a1, a2 + a3) * q3;                           \
            float n4 = (a3 + a4) * qB;                                        \
            a0 = n0; a1 = n1; a2 = n2; a3 = n3;                               \
            a4 = (lane == 31) ? n4 : 0.0f;                                    \
        }

#define FWD_STEP_PIPE(rnext)                                                  \
        {                                                                     \
            float tB, t1, t3;                                                 \
            QLDS_TO(rnext, tB, t1, t3);                                       \
            FWD_DP();                                                         \
            qB = tB; q1 = t1; q3 = t3;                                        \
        }

#define BWD_DP()                                                              \
        {                                                                     \
            float c1 = a1 * pq1;                                              \
            float c3 = a3 * pq3;                                              \
            float cB2 = a2 * pqB;                                             \
            float w = c1 * sk1;                                               \
            float wd = __shfl_down_sync(0xffffffffu, w, 1) * sc;              \
            float b0d = __shfl_down_sync(0xffffffffu, a0, 1) * sc;            \
            float t1 = (lane == 31) ? a4 : b0d;                               \
            float t2 = (lane == 31) ? 0.0f : wd;                              \
            float n0 = fmaf(a0, pqB, c1);                                     \
            float n1 = fmaf(c3, sk3, c1 + cB2);                               \
            float n2 = cB2 + c3;                                              \
            float n3 = fmaf(t1, pqB, c3 + t2);                                \
            float n4 = a4 * pqB;                                              \
            a0 = n0; a1 = n1; a2 = n2; a3 = n3; a4 = n4;                      \
            pqB = qB; pq1 = q1; pq3 = q3;                                     \
        }

#define SH_UP   __shfl_up_sync(0xffffffffu, K, 1)
#define SH_DN   __shfl_down_sync(0xffffffffu, K, 1)

        NBAR(barid);                               // wait: block 0 staged
        if (fwd) {
            {   // block 0: row 0 is init, rows 1..7 are DP steps 1..7
                const float* sst = sstP;
                QLDS_TO(0, qB, q1, q3);
                if (lane == 0) { a0 = qB; a1 = q1; }   // alpha'_0
                QLDS_TO(1, qB, q1, q3);
                FWD_STEP_PIPE(2); FWD_STEP_PIPE(3); FWD_STEP_PIPE(4);
                FWD_STEP_PIPE(5); FWD_STEP_PIPE(6); FWD_STEP_PIPE(7);
                FWD_DP(); RENORM(SH_UP);
            }
            NBAR(barid);
            for (int c = 1; c < 64; ++c) {
                const float* sst = sstP + (c & 1) * 1024;
                QLDS_TO(0, qB, q1, q3);
                FWD_STEP_PIPE(1); FWD_STEP_PIPE(2); FWD_STEP_PIPE(3);
                FWD_STEP_PIPE(4); FWD_STEP_PIPE(5); FWD_STEP_PIPE(6);
                FWD_STEP_PIPE(7);
                FWD_DP(); RENORM(SH_UP);
                NBAR(barid);
            }
        } else {
            {   // block 0: row 0 loads q(1023) into pq + init, rows 1..7 DP
                const float* sst = sstP;
                QLDS_TO(0, qB, q1, q3);
                pqB = qB; pq1 = q1; pq3 = q3;
                if (lane == 31) { a3 = 1.0f; a4 = 1.0f; }  // beta_1023
                QLDS_TO(1, qB, q1, q3); BWD_DP();
                QLDS_TO(2, qB, q1, q3); BWD_DP();
                QLDS_TO(3, qB, q1, q3); BWD_DP();
                QLDS_TO(4, qB, q1, q3); BWD_DP();
                QLDS_TO(5, qB, q1, q3); BWD_DP();
                QLDS_TO(6, qB, q1, q3); BWD_DP();
                QLDS_TO(7, qB, q1, q3); BWD_DP();
                RENORM(SH_DN);
            }
            NBAR(barid);
            for (int c = 1; c < 64; ++c) {
                const float* sst = sstP + (c & 1) * 1024;
                QLDS_TO(0, qB, q1, q3); BWD_DP();
                QLDS_TO(1, qB, q1, q3); BWD_DP();
                QLDS_TO(2, qB, q1, q3); BWD_DP();
                QLDS_TO(3, qB, q1, q3); BWD_DP();
                QLDS_TO(4, qB, q1, q3); BWD_DP();
                QLDS_TO(5, qB, q1, q3); BWD_DP();
                QLDS_TO(6, qB, q1, q3); BWD_DP();
                QLDS_TO(7, qB, q1, q3); BWD_DP();
                RENORM(SH_DN);
                NBAR(barid);
            }
            float Kf = (float)K;
            sbeta[e][4 * lane + 0] = lg2(a0) + Kf;
            sbeta[e][4 * lane + 1] = lg2(a1) + Kf;
            sbeta[e][4 * lane + 2] = lg2(a2) + Kf;
            sbeta[e][4 * lane + 3] = lg2(a3) + Kf;
            if (lane == 31) sbeta[e][128] = lg2(a4) + Kf;
        }
        __syncthreads();

        if (fwd) {
            // loglik = (LSE_s(log2 alpha'_511 + log2 beta'_511) - szTot)*ln2
            float Kf = (float)K;
            float c0 = lg2(a0) + Kf + sbeta[e][4 * lane + 0];
            float c1 = lg2(a1) + Kf + sbeta[e][4 * lane + 1];
            float c2 = lg2(a2) + Kf + sbeta[e][4 * lane + 2];
            float c3 = lg2(a3) + Kf + sbeta[e][4 * lane + 3];
            float c4 = (lane == 31) ? (lg2(a4) + Kf + sbeta[e][128]) : NEG;
            float m = fmaxf(fmaxf(fmaxf(c0, c1), fmaxf(c2, c3)), c4);
#pragma unroll
            for (int off = 16; off; off >>= 1)
                m = fmaxf(m, __shfl_xor_sync(0xffffffffu, m, off));
            float s = ex2(c0 - m) + ex2(c1 - m) + ex2(c2 - m)
                    + ex2(c3 - m) + ex2(c4 - m);
#pragma unroll
            for (int off = 16; off; off >>= 1)
                s += __shfl_xor_sync(0xffffffffu, s, off);
            if (lane == 0) {
                float szTot = szHalf[2 * e] + szHalf[2 * e + 1];
                float loglik = (m + lg2(s) - szTot) * LN2_;
                float loss = -loglik;
                float pp = expf(-loss);
                float om = 1.0f - pp;
                sfocal[e] = 0.25f * om * om * loss;
            }
        }
    }
    __syncthreads();

    // ---- fused mean: last CTA reduces all 256 focal values in parallel ----
    if (threadIdx.x == 0) {
        const int b0 = blockIdx.x << 1;
        g_focal[b0] = sfocal[0];
        g_focal[b0 + 1] = sfocal[1];
        __threadfence();
        unsigned int old = atomicAdd(&g_count, 1u);
        sIsLast = (old == gridDim.x - 1) ? 1u : 0u;
    }
    __syncthreads();
    if (sIsLast && threadIdx.x < 128) {
        float v = g_focal[threadIdx.x] + g_focal[threadIdx.x + 128];
#pragma unroll
        for (int off = 16; off; off >>= 1)
            v += __shfl_xor_sync(0xffffffffu, v, off);
        if (lane == 0) sred[wid] = v;
    }
    __syncthreads();
    if (sIsLast && threadIdx.x == 0) {
        out[0] = ((sred[0] + sred[1]) + (sred[2] + sred[3])) * (1.0f / (float)B_);
        g_count = 0;                 // reset for next graph replay
    }
}

extern "C" void kernel_launch(void* const* d_in, const int* in_sizes, int n_in,
                              void* d_out, int out_size) {
    const int* y_true;
    const float* y_pred;
    if (in_sizes[0] == B_ * L_) {
        y_true = (const int*)d_in[0];
        y_pred = (const float*)d_in[1];
    } else {
        y_true = (const int*)d_in[1];
        y_pred = (const float*)d_in[0];
    }
    ctc_kernel<<<B_ / 2, 256>>>(y_true, y_pred, (float*)d_out);
}